// round 3
// baseline (speedup 1.0000x reference)
#include <cuda_runtime.h>
#include <cuda_fp16.h>
#include <cstdint>

#define MDIM 16384
#define NDIM 1024
#define KDIM 4096

#define BM 128
#define BN 128
#define BK 64
#define NSTAGE 3
#define KT (KDIM / BK)              // 64 k-tiles
#define SSTRIDE 72                  // halves per smem row (64 + 8 pad) -> 144 B
#define A_STAGE_B (BM * SSTRIDE * 2)        // 18432
#define STAGE_B   (2 * A_STAGE_B)           // 36864 (A then B)
#define SMEM_BYTES (1024 + NSTAGE * STAGE_B)  // 111616

// ---------------- device scratch (static globals: allowed) ----------------
__device__ __align__(16) uint16_t g_h[(size_t)MDIM * KDIM];   // fp16 hidden (128 MB)
__device__ __align__(16) uint16_t g_w[(size_t)NDIM * KDIM];   // fp16 w_int  (8 MB)
__device__ float g_scale[NDIM];

// ---------------- PTX helpers ----------------
__device__ __forceinline__ uint32_t smem_u32(const void* p) {
    uint32_t a;
    asm("{ .reg .u64 t; cvta.to.shared.u64 t, %1; cvt.u32.u64 %0, t; }" : "=r"(a) : "l"(p));
    return a;
}
__device__ __forceinline__ void cp16(uint32_t dst, const void* src) {
    asm volatile("cp.async.cg.shared.global [%0], [%1], 16;" :: "r"(dst), "l"(src));
}
__device__ __forceinline__ void cp_commit() {
    asm volatile("cp.async.commit_group;" ::: "memory");
}
template <int N> __device__ __forceinline__ void cp_wait() {
    asm volatile("cp.async.wait_group %0;" :: "n"(N) : "memory");
}
__device__ __forceinline__ void mma16816(float& d0, float& d1, float& d2, float& d3,
                                         uint32_t a0, uint32_t a1, uint32_t a2, uint32_t a3,
                                         uint32_t b0, uint32_t b1) {
    asm volatile(
        "mma.sync.aligned.m16n8k16.row.col.f32.f16.f16.f32 "
        "{%0,%1,%2,%3}, {%4,%5,%6,%7}, {%8,%9}, {%0,%1,%2,%3};"
        : "+f"(d0), "+f"(d1), "+f"(d2), "+f"(d3)
        : "r"(a0), "r"(a1), "r"(a2), "r"(a3), "r"(b0), "r"(b1));
}

// ---------------- kernel 1: per-channel weight fake-quant -> exact-int fp16 ----------------
__global__ void quantize_w_kernel(const float* __restrict__ W) {
    int d = blockIdx.x;
    int tid = threadIdx.x;
    const float* row = W + (size_t)d * KDIM;

    float m = 0.f;
    for (int k = tid; k < KDIM; k += 256) m = fmaxf(m, fabsf(row[k]));
    #pragma unroll
    for (int o = 16; o; o >>= 1) m = fmaxf(m, __shfl_xor_sync(0xffffffffu, m, o));

    __shared__ float red[8];
    if ((tid & 31) == 0) red[tid >> 5] = m;
    __syncthreads();
    if (tid < 8) {
        float v = red[tid];
        #pragma unroll
        for (int o = 4; o; o >>= 1) v = fmaxf(v, __shfl_xor_sync(0xffu, v, o));
        if (tid == 0) red[0] = v;
    }
    __syncthreads();

    float scale = fmaxf(red[0], 1e-8f) / 127.f;
    if (tid == 0) g_scale[d] = scale;

    __half* wout = reinterpret_cast<__half*>(g_w) + (size_t)d * KDIM;
    for (int k = tid; k < KDIM; k += 256) {
        float q = rintf(row[k] / scale);               // round-half-even == jnp.round
        q = fminf(fmaxf(q, -128.f), 127.f);
        wout[k] = __float2half_rn(q);                  // |q| <= 128: exact in fp16
    }
}

// ---------------- kernel 2: hidden fp32 -> fp16 ----------------
__global__ void convert_h_kernel(const float* __restrict__ H) {
    size_t i = (size_t)blockIdx.x * blockDim.x + threadIdx.x;  // over float4s
    float4 v = reinterpret_cast<const float4*>(H)[i];
    __half2* out = reinterpret_cast<__half2*>(g_h);
    out[2 * i]     = __floats2half2_rn(v.x, v.y);
    out[2 * i + 1] = __floats2half2_rn(v.z, v.w);
}

// ---------------- kernel 3: fp16 mma.sync GEMM + scale/bias/residual epilogue ----------------
// CTA 128x128, BK=64, 8 warps in 2(m) x 4(n), warp tile 64x32, m16n8k16.
// smem: [0,512) scale, [512,1024) bias, stages at 1024 (A 128x72h, B 128x72h per stage).
__device__ __forceinline__ void load_stage(uint32_t stage_base, int tid, int m0, int n0, int t) {
    int k0 = t * BK;
    const __half* Ab = reinterpret_cast<const __half*>(g_h) + (size_t)m0 * KDIM + k0;
    #pragma unroll
    for (int i = 0; i < 4; i++) {
        int cid = i * 256 + tid;          // 1024 chunks of 16B
        int row = cid >> 3, col = cid & 7;
        cp16(stage_base + row * (SSTRIDE * 2) + col * 16, Ab + (size_t)row * KDIM + col * 8);
    }
    const __half* Bb = reinterpret_cast<const __half*>(g_w) + (size_t)n0 * KDIM + k0;
    uint32_t bbase = stage_base + A_STAGE_B;
    #pragma unroll
    for (int i = 0; i < 4; i++) {
        int cid = i * 256 + tid;
        int row = cid >> 3, col = cid & 7;
        cp16(bbase + row * (SSTRIDE * 2) + col * 16, Bb + (size_t)row * KDIM + col * 8);
    }
}

__global__ void __launch_bounds__(256, 2) gemm_kernel(const float* __restrict__ bias,
                                                      const float* __restrict__ input,
                                                      float* __restrict__ out) {
    extern __shared__ char smem[];
    uint32_t sb = smem_u32(smem);
    int tid = threadIdx.x;
    int wid = tid >> 5, lane = tid & 31;
    int g = lane >> 2, c = lane & 3;      // mma group / thread-in-group
    int wm = wid & 1, wn = wid >> 1;      // 2 x 4 warp grid

    int mtile = blockIdx.x >> 3;          // 128 m-tiles
    int ntile = blockIdx.x & 7;           // 8 n-tiles (adjacent bids share A tile in L2)
    int m0 = mtile * BM, n0 = ntile * BN;

    float* s_scale = reinterpret_cast<float*>(smem);
    float* s_bias  = reinterpret_cast<float*>(smem + 512);
    for (int j = tid; j < BN; j += 256) {
        s_scale[j] = g_scale[n0 + j];
        s_bias[j]  = bias[n0 + j];
    }

    // prologue
    #pragma unroll
    for (int s = 0; s < NSTAGE; s++) {
        load_stage(sb + 1024u + (uint32_t)s * STAGE_B, tid, m0, n0, s);
        cp_commit();
    }

    float acc[4][4][4];
    #pragma unroll
    for (int mt = 0; mt < 4; mt++)
        #pragma unroll
        for (int nt = 0; nt < 4; nt++)
            #pragma unroll
            for (int r = 0; r < 4; r++) acc[mt][nt][r] = 0.f;

    for (int t = 0; t < KT; t++) {
        int s = t % NSTAGE;
        const uint32_t* As = reinterpret_cast<const uint32_t*>(smem + 1024 + (size_t)s * STAGE_B);
        const uint32_t* Bs = As + A_STAGE_B / 4;

        cp_wait<NSTAGE - 1>();
        __syncthreads();

        #pragma unroll
        for (int ks = 0; ks < 4; ks++) {           // k offset ks*16 within BK=64
            int kb = ks * 8 + c;                   // b32 index within row
            uint32_t a[4][4], b[4][2];
            #pragma unroll
            for (int mt = 0; mt < 4; mt++) {
                int rm = wm * 64 + mt * 16;
                a[mt][0] = As[(rm + g)     * (SSTRIDE / 2) + kb];
                a[mt][1] = As[(rm + 8 + g) * (SSTRIDE / 2) + kb];
                a[mt][2] = As[(rm + g)     * (SSTRIDE / 2) + kb + 4];
                a[mt][3] = As[(rm + 8 + g) * (SSTRIDE / 2) + kb + 4];
            }
            #pragma unroll
            for (int nt = 0; nt < 4; nt++) {
                int rn = wn * 32 + nt * 8;
                b[nt][0] = Bs[(rn + g) * (SSTRIDE / 2) + kb];
                b[nt][1] = Bs[(rn + g) * (SSTRIDE / 2) + kb + 4];
            }
            #pragma unroll
            for (int mt = 0; mt < 4; mt++)
                #pragma unroll
                for (int nt = 0; nt < 4; nt++)
                    mma16816(acc[mt][nt][0], acc[mt][nt][1], acc[mt][nt][2], acc[mt][nt][3],
                             a[mt][0], a[mt][1], a[mt][2], a[mt][3], b[nt][0], b[nt][1]);
        }

        __syncthreads();                 // everyone done reading stage s
        if (t + NSTAGE < KT)
            load_stage(sb + 1024u + (uint32_t)s * STAGE_B, tid, m0, n0, t + NSTAGE);
        cp_commit();                     // empty group in tail keeps accounting exact
    }

    // epilogue: out = acc * scale[n] + bias[n] + input
    #pragma unroll
    for (int mt = 0; mt < 4; mt++) {
        #pragma unroll
        for (int nt = 0; nt < 4; nt++) {
            int nl = wn * 32 + nt * 8 + 2 * c;
            int n  = n0 + nl;
            float sc0 = s_scale[nl],     sc1 = s_scale[nl + 1];
            float bi0 = s_bias[nl],      bi1 = s_bias[nl + 1];
            int mA = m0 + wm * 64 + mt * 16 + g;
            int mB = mA + 8;

            const float2* inA = reinterpret_cast<const float2*>(input + (size_t)mA * NDIM + n);
            const float2* inB = reinterpret_cast<const float2*>(input + (size_t)mB * NDIM + n);
            float2* outA = reinterpret_cast<float2*>(out + (size_t)mA * NDIM + n);
            float2* outB = reinterpret_cast<float2*>(out + (size_t)mB * NDIM + n);

            float2 ia = *inA, ib = *inB, oa, ob;
            oa.x = acc[mt][nt][0] * sc0 + bi0 + ia.x;
            oa.y = acc[mt][nt][1] * sc1 + bi1 + ia.y;
            ob.x = acc[mt][nt][2] * sc0 + bi0 + ib.x;
            ob.y = acc[mt][nt][3] * sc1 + bi1 + ib.y;
            *outA = oa;
            *outB = ob;
        }
    }
}

// ---------------- launch ----------------
extern "C" void kernel_launch(void* const* d_in, const int* in_sizes, int n_in,
                              void* d_out, int out_size) {
    const float* hidden = (const float*)d_in[0];   // [16,1024,4096]
    const float* input  = (const float*)d_in[1];   // [16,1024,1024]
    const float* W      = (const float*)d_in[2];   // [1024,4096]
    const float* b      = (const float*)d_in[3];   // [1024]
    float* out = (float*)d_out;

    quantize_w_kernel<<<NDIM, 256>>>(W);
    convert_h_kernel<<<(size_t)MDIM * KDIM / 4 / 256, 256>>>(hidden);

    cudaFuncSetAttribute(gemm_kernel, cudaFuncAttributeMaxDynamicSharedMemorySize, SMEM_BYTES);
    gemm_kernel<<<(MDIM / BM) * (NDIM / BN), 256, SMEM_BYTES>>>(b, input, out);
}

// round 4
// speedup vs baseline: 1.0981x; 1.0981x over previous
#include <cuda_runtime.h>
#include <cuda_fp16.h>
#include <cstdint>

#define MDIM 16384
#define NDIM 1024
#define KDIM 4096

#define BM 128
#define BN 128
#define BK 64
#define NSTAGE 3
#define KT (KDIM / BK)              // 64 k-tiles
#define SSTRIDE 72                  // halves per smem row (64 + 8 pad) -> 144 B
#define ROWB (SSTRIDE * 2)          // 144 bytes per row
#define A_STAGE_B (BM * ROWB)       // 18432
#define STAGE_B   (2 * A_STAGE_B)   // 36864 (A then B)
#define SMEM_BYTES (1024 + NSTAGE * STAGE_B)  // 111616

// ---------------- device scratch ----------------
__device__ __align__(16) uint16_t g_h[(size_t)MDIM * KDIM];   // fp16 hidden (128 MB)
__device__ __align__(16) uint16_t g_w[(size_t)NDIM * KDIM];   // fp16 w_int  (8 MB)
__device__ float g_scale[NDIM];

// ---------------- PTX helpers ----------------
__device__ __forceinline__ uint32_t smem_u32(const void* p) {
    uint32_t a;
    asm("{ .reg .u64 t; cvta.to.shared.u64 t, %1; cvt.u32.u64 %0, t; }" : "=r"(a) : "l"(p));
    return a;
}
__device__ __forceinline__ void cp16(uint32_t dst, const void* src) {
    asm volatile("cp.async.cg.shared.global [%0], [%1], 16;" :: "r"(dst), "l"(src));
}
__device__ __forceinline__ void cp_commit() {
    asm volatile("cp.async.commit_group;" ::: "memory");
}
template <int N> __device__ __forceinline__ void cp_wait() {
    asm volatile("cp.async.wait_group %0;" :: "n"(N) : "memory");
}
__device__ __forceinline__ void ldsm4(uint32_t& r0, uint32_t& r1, uint32_t& r2, uint32_t& r3,
                                      uint32_t addr) {
    asm volatile("ldmatrix.sync.aligned.m8n8.x4.shared.b16 {%0,%1,%2,%3}, [%4];"
                 : "=r"(r0), "=r"(r1), "=r"(r2), "=r"(r3) : "r"(addr));
}
__device__ __forceinline__ void mma16816(float& d0, float& d1, float& d2, float& d3,
                                         uint32_t a0, uint32_t a1, uint32_t a2, uint32_t a3,
                                         uint32_t b0, uint32_t b1) {
    asm volatile(
        "mma.sync.aligned.m16n8k16.row.col.f32.f16.f16.f32 "
        "{%0,%1,%2,%3}, {%4,%5,%6,%7}, {%8,%9}, {%0,%1,%2,%3};"
        : "+f"(d0), "+f"(d1), "+f"(d2), "+f"(d3)
        : "r"(a0), "r"(a1), "r"(a2), "r"(a3), "r"(b0), "r"(b1));
}

// ---------------- kernel 1: fused W fake-quant + H fp32->fp16 convert ----------------
// blocks [0,1024): one W output-channel each (max-abs reduce -> scale -> exact-int fp16)
// blocks [1024, 1024+65536): H conversion, one float4 per thread
__global__ void prep_kernel(const float* __restrict__ W, const float* __restrict__ H) {
    int tid = threadIdx.x;
    if (blockIdx.x < NDIM) {
        int d = blockIdx.x;
        const float* row = W + (size_t)d * KDIM;

        float m = 0.f;
        for (int k = tid; k < KDIM; k += 256) m = fmaxf(m, fabsf(row[k]));
        #pragma unroll
        for (int o = 16; o; o >>= 1) m = fmaxf(m, __shfl_xor_sync(0xffffffffu, m, o));

        __shared__ float red[8];
        if ((tid & 31) == 0) red[tid >> 5] = m;
        __syncthreads();
        if (tid < 8) {
            float v = red[tid];
            #pragma unroll
            for (int o = 4; o; o >>= 1) v = fmaxf(v, __shfl_xor_sync(0xffu, v, o));
            if (tid == 0) red[0] = v;
        }
        __syncthreads();

        float scale = fmaxf(red[0], 1e-8f) / 127.f;
        if (tid == 0) g_scale[d] = scale;

        __half* wout = reinterpret_cast<__half*>(g_w) + (size_t)d * KDIM;
        for (int k = tid; k < KDIM; k += 256) {
            float q = rintf(row[k] / scale);           // round-half-even == jnp.round
            q = fminf(fmaxf(q, -128.f), 127.f);
            wout[k] = __float2half_rn(q);              // |q| <= 128: exact in fp16
        }
    } else {
        size_t i = (size_t)(blockIdx.x - NDIM) * 256 + tid;   // float4 index
        float4 v = reinterpret_cast<const float4*>(H)[i];
        __half2* outp = reinterpret_cast<__half2*>(g_h);
        outp[2 * i]     = __floats2half2_rn(v.x, v.y);
        outp[2 * i + 1] = __floats2half2_rn(v.z, v.w);
    }
}

// ---------------- kernel 2: fp16 mma.sync GEMM + scale/bias/residual epilogue ----------------
// CTA 128x128, BK=64, 8 warps in 2(m) x 4(n), warp tile 64x32, m16n8k16, ldmatrix feeds.
__device__ __forceinline__ void load_stage(uint32_t stage_base, int tid, int m0, int n0, int t) {
    int k0 = t * BK;
    const __half* Ab = reinterpret_cast<const __half*>(g_h) + (size_t)m0 * KDIM + k0;
    #pragma unroll
    for (int i = 0; i < 4; i++) {
        int cid = i * 256 + tid;          // 1024 chunks of 16B
        int row = cid >> 3, col = cid & 7;
        cp16(stage_base + row * ROWB + col * 16, Ab + (size_t)row * KDIM + col * 8);
    }
    const __half* Bb = reinterpret_cast<const __half*>(g_w) + (size_t)n0 * KDIM + k0;
    uint32_t bbase = stage_base + A_STAGE_B;
    #pragma unroll
    for (int i = 0; i < 4; i++) {
        int cid = i * 256 + tid;
        int row = cid >> 3, col = cid & 7;
        cp16(bbase + row * ROWB + col * 16, Bb + (size_t)row * KDIM + col * 8);
    }
}

__global__ void __launch_bounds__(256, 2) gemm_kernel(const float* __restrict__ bias,
                                                      const float* __restrict__ input,
                                                      float* __restrict__ out) {
    extern __shared__ char smem[];
    uint32_t sb = smem_u32(smem);
    int tid = threadIdx.x;
    int wid = tid >> 5, lane = tid & 31;
    int g = lane >> 2, c = lane & 3;      // mma group / thread-in-group
    int wm = wid & 1, wn = wid >> 1;      // 2 x 4 warp grid

    int mtile = blockIdx.x >> 3;          // 128 m-tiles
    int ntile = blockIdx.x & 7;           // 8 n-tiles (adjacent bids share A tile in L2)
    int m0 = mtile * BM, n0 = ntile * BN;

    float* s_scale = reinterpret_cast<float*>(smem);
    float* s_bias  = reinterpret_cast<float*>(smem + 512);
    for (int j = tid; j < BN; j += 256) {
        s_scale[j] = g_scale[n0 + j];
        s_bias[j]  = bias[n0 + j];
    }

    // per-lane ldmatrix byte offsets (within a stage)
    // A: x4 covers one 16x16 m-tile: lanes 0-15 -> rows, lanes 16-31 -> +8 half-cols
    uint32_t a_loff = (uint32_t)((wm * 64 + (lane & 15)) * ROWB + (lane >> 4) * 16);
    // B: x4 covers two n-tiles (16 rows): lanes {0-7,8-15,16-23,24-31} ->
    //    {rows+0 col+0, rows+0 col+8, rows+8 col+0, rows+8 col+8}
    uint32_t b_loff = (uint32_t)(A_STAGE_B +
                      (wn * 32 + (lane >> 4) * 8 + (lane & 7)) * ROWB +
                      (((lane >> 3) & 1) * 16));

    // prologue
    #pragma unroll
    for (int s = 0; s < NSTAGE; s++) {
        load_stage(sb + 1024u + (uint32_t)s * STAGE_B, tid, m0, n0, s);
        cp_commit();
    }

    float acc[4][4][4];
    #pragma unroll
    for (int mt = 0; mt < 4; mt++)
        #pragma unroll
        for (int nt = 0; nt < 4; nt++)
            #pragma unroll
            for (int r = 0; r < 4; r++) acc[mt][nt][r] = 0.f;

    for (int t = 0; t < KT; t++) {
        int s = t % NSTAGE;
        uint32_t stage = sb + 1024u + (uint32_t)s * STAGE_B;

        cp_wait<NSTAGE - 1>();
        __syncthreads();

        #pragma unroll
        for (int ks = 0; ks < 4; ks++) {           // k offset ks*16 within BK=64
            uint32_t a[4][4], b[2][4];
            #pragma unroll
            for (int mt = 0; mt < 4; mt++)
                ldsm4(a[mt][0], a[mt][1], a[mt][2], a[mt][3],
                      stage + a_loff + (uint32_t)(mt * 16 * ROWB) + (uint32_t)(ks * 32));
            #pragma unroll
            for (int p = 0; p < 2; p++)
                ldsm4(b[p][0], b[p][1], b[p][2], b[p][3],
                      stage + b_loff + (uint32_t)(p * 16 * ROWB) + (uint32_t)(ks * 32));
            #pragma unroll
            for (int mt = 0; mt < 4; mt++)
                #pragma unroll
                for (int nt = 0; nt < 4; nt++) {
                    int p = nt >> 1, q = nt & 1;
                    mma16816(acc[mt][nt][0], acc[mt][nt][1], acc[mt][nt][2], acc[mt][nt][3],
                             a[mt][0], a[mt][1], a[mt][2], a[mt][3],
                             b[p][2 * q], b[p][2 * q + 1]);
                }
        }

        __syncthreads();                 // everyone done reading stage s
        if (t + NSTAGE < KT)
            load_stage(stage, tid, m0, n0, t + NSTAGE);
        cp_commit();                     // empty group in tail keeps accounting exact
    }

    // epilogue: out = acc * scale[n] + bias[n] + input
    #pragma unroll
    for (int mt = 0; mt < 4; mt++) {
        #pragma unroll
        for (int nt = 0; nt < 4; nt++) {
            int nl = wn * 32 + nt * 8 + 2 * c;
            int n  = n0 + nl;
            float sc0 = s_scale[nl],     sc1 = s_scale[nl + 1];
            float bi0 = s_bias[nl],      bi1 = s_bias[nl + 1];
            int mA = m0 + wm * 64 + mt * 16 + g;
            int mB = mA + 8;

            const float2* inA = reinterpret_cast<const float2*>(input + (size_t)mA * NDIM + n);
            const float2* inB = reinterpret_cast<const float2*>(input + (size_t)mB * NDIM + n);
            float2* outA = reinterpret_cast<float2*>(out + (size_t)mA * NDIM + n);
            float2* outB = reinterpret_cast<float2*>(out + (size_t)mB * NDIM + n);

            float2 ia = *inA, ib = *inB, oa, ob;
            oa.x = acc[mt][nt][0] * sc0 + bi0 + ia.x;
            oa.y = acc[mt][nt][1] * sc1 + bi1 + ia.y;
            ob.x = acc[mt][nt][2] * sc0 + bi0 + ib.x;
            ob.y = acc[mt][nt][3] * sc1 + bi1 + ib.y;
            *outA = oa;
            *outB = ob;
        }
    }
}

// ---------------- launch ----------------
extern "C" void kernel_launch(void* const* d_in, const int* in_sizes, int n_in,
                              void* d_out, int out_size) {
    const float* hidden = (const float*)d_in[0];   // [16,1024,4096]
    const float* input  = (const float*)d_in[1];   // [16,1024,1024]
    const float* W      = (const float*)d_in[2];   // [1024,4096]
    const float* b      = (const float*)d_in[3];   // [1024]
    float* out = (float*)d_out;

    prep_kernel<<<NDIM + (int)((size_t)MDIM * KDIM / 4 / 256), 256>>>(W, hidden);

    cudaFuncSetAttribute(gemm_kernel, cudaFuncAttributeMaxDynamicSharedMemorySize, SMEM_BYTES);
    gemm_kernel<<<(MDIM / BM) * (NDIM / BN), 256, SMEM_BYTES>>>(b, input, out);
}